// round 16
// baseline (speedup 1.0000x reference)
#include <cuda_runtime.h>

#define FULLMASK 0xffffffffu
#define ITERS 4   // points per warp; CTA covers 32 points
#define FPAD 12   // words per sF row (4 hi + 4 lo + 4 pad) -> conflict-free

// ---- packed per-point data: one 32B-aligned record ----
struct __align__(32) PtData { float4 c; float4 n; };
__device__ PtData g_pt[50048];

__global__ __launch_bounds__(256) void pack_kernel(
    const float* __restrict__ pos,
    const float* __restrict__ normals,
    const float* __restrict__ stddev,
    int N)
{
    int i = blockIdx.x * 256 + threadIdx.x;
    if (i >= N) return;
    float4 a, b;
    a.x = pos[3*i+0]; a.y = pos[3*i+1]; a.z = pos[3*i+2]; a.w = stddev[i];
    b.x = normals[3*i+0]; b.y = normals[3*i+1]; b.z = normals[3*i+2]; b.w = 0.0f;
    g_pt[i].c = a;
    g_pt[i].n = b;
}

__device__ __forceinline__ void ldg256(const PtData* p, float4& a, float4& b) {
    asm("ld.global.nc.v8.f32 {%0,%1,%2,%3,%4,%5,%6,%7}, [%8];"
        : "=f"(a.x), "=f"(a.y), "=f"(a.z), "=f"(a.w),
          "=f"(b.x), "=f"(b.y), "=f"(b.z), "=f"(b.w)
        : "l"(p));
}
__device__ __forceinline__ unsigned pack2(float lo, float hi) {
    unsigned r;
    asm("cvt.rn.f16x2.f32 %0, %1, %2;" : "=r"(r) : "f"(hi), "f"(lo));
    return r;
}
__device__ __forceinline__ void unpack2(unsigned v, float& lo, float& hi) {
    asm("{ .reg .f16 l, h; mov.b32 {l, h}, %2; cvt.f32.f16 %0, l; cvt.f32.f16 %1, h; }"
        : "=f"(lo), "=f"(hi) : "r"(v));
}
__device__ __forceinline__ unsigned smem_u32(const void* p) {
    unsigned a;
    asm("{ .reg .u64 t; cvta.to.shared.u64 t, %1; cvt.u32.u64 %0, t; }" : "=r"(a) : "l"(p));
    return a;
}
__device__ __forceinline__ void ldsm4(unsigned& r0, unsigned& r1,
                                      unsigned& r2, unsigned& r3, unsigned addr) {
    asm volatile("ldmatrix.sync.aligned.m8n8.x4.shared.b16 {%0,%1,%2,%3}, [%4];"
        : "=r"(r0), "=r"(r1), "=r"(r2), "=r"(r3) : "r"(addr));
}
__device__ __forceinline__ void mma16(float& d0, float& d1, float& d2, float& d3,
                                      unsigned a0, unsigned a1, unsigned a2, unsigned a3,
                                      unsigned b0, unsigned b1) {
    asm volatile(
        "mma.sync.aligned.m16n8k16.row.col.f32.f16.f16.f32 "
        "{%0,%1,%2,%3}, {%4,%5,%6,%7}, {%8,%9}, {%0,%1,%2,%3};"
        : "+f"(d0), "+f"(d1), "+f"(d2), "+f"(d3)
        : "r"(a0), "r"(a1), "r"(a2), "r"(a3), "r"(b0), "r"(b1));
}
__device__ __forceinline__ void mma8h(float* d, unsigned a0, unsigned a1, unsigned b0) {
    asm volatile(
        "mma.sync.aligned.m16n8k8.row.col.f32.f16.f16.f32 "
        "{%0,%1,%2,%3}, {%4,%5}, {%6}, {%0,%1,%2,%3};"
        : "+f"(d[0]), "+f"(d[1]), "+f"(d[2]), "+f"(d[3])
        : "r"(a0), "r"(a1), "r"(b0));
}

__global__ __launch_bounds__(256, 4) void normal_est_kernel(
    const float* __restrict__ old_w,    // N*32
    const int*   __restrict__ dense_l,  // N*32
    const float* __restrict__ W1g,      // (7,32)
    const float* __restrict__ b1g,      // (32,)
    const float* __restrict__ W2g,      // (64,32)
    const float* __restrict__ b2g,      // (32,)
    const float* __restrict__ W3g,      // (32,)
    const float* __restrict__ b3g,      // (1,)
    float* __restrict__ out_normals,
    float* __restrict__ out_weights,
    int N)
{
    __shared__ __align__(16) unsigned sF[8][32][FPAD]; // feature rows: 4 hi + 4 lo f16x2
    __shared__ unsigned sW1h[4][32];    // W1 B frags (m16n8k8), f16 hi
    __shared__ unsigned sW1l[4][32];    // W1 lo residue
    __shared__ unsigned sBh[16][64];    // W2 B frags (m16n8k16) hi
    __shared__ unsigned sBl[8][64];     // W2b lo residue (kt 2..3)
    __shared__ unsigned sGh[8][16];     // per-warp g as f16x2 pairs
    __shared__ __align__(8)  float sGd[8][36];  // per-point gd+b2 (batched)
    __shared__ __align__(16) float sG[8][32];   // wgt redistribution
    __shared__ __align__(16) float sEp[64];     // interleaved [b2[j], W3[j]]
    __shared__ __align__(8)  float sB1v[32];
    __shared__            float    sB3;
    __shared__            float    sCov[32][8];

    const int tid  = threadIdx.x;
    const int lane = tid & 31;
    const int warp = tid >> 5;
    const int lp   = lane & 3;      // quad-lane
    const int lq   = lane >> 2;     // quad-row

    // ---- W2 fragments (m16n8k16), hi + lo residue for kt>=2 ----
    for (int it = tid; it < 512; it += 256) {
        const int frag = it >> 5, l2 = it & 31;
        const int lp2 = l2 & 3, lq2 = l2 >> 2;
        const int kt = frag >> 2, nt = frag & 3;
        const int n  = nt * 8 + lq2;
        const int k0 = kt * 16 + 2 * lp2;
        const float w00 = W2g[(k0    ) * 32 + n], w01 = W2g[(k0 + 1) * 32 + n];
        const float w10 = W2g[(k0 + 8) * 32 + n], w11 = W2g[(k0 + 9) * 32 + n];
        const unsigned p0 = pack2(w00, w01), p1 = pack2(w10, w11);
        sBh[frag][2*l2  ] = p0;
        sBh[frag][2*l2+1] = p1;
        if (kt >= 2) {
            float r00, r01, r10, r11;
            unpack2(p0, r00, r01); unpack2(p1, r10, r11);
            sBl[frag-8][2*l2  ] = pack2(w00 - r00, w01 - r01);
            sBl[frag-8][2*l2+1] = pack2(w10 - r10, w11 - r11);
        }
    }
    // ---- W1 fragments (m16n8k8), hi + lo (K rows 0..7, row 7 = 0 pad) ----
    if (tid < 128) {
        const int nt = tid >> 5, l2 = tid & 31;
        const int lp2 = l2 & 3, lq2 = l2 >> 2;
        const int n  = nt * 8 + lq2;
        const int k0 = 2 * lp2;
        const float w0 = W1g[k0 * 32 + n];
        const float w1 = (k0 + 1 < 7) ? W1g[(k0 + 1) * 32 + n] : 0.0f;
        const unsigned ph = pack2(w0, w1);
        float r0, r1; unpack2(ph, r0, r1);
        sW1h[nt][l2] = ph;
        sW1l[nt][l2] = pack2(w0 - r0, w1 - r1);
    }
    if (tid < 32) {
        sEp[2*tid] = b2g[tid]; sEp[2*tid+1] = W3g[tid];
        sB1v[tid] = b1g[tid];
    }
    if (tid == 0) sB3 = b3g[0];
    __syncthreads();

    const float b3v = sB3;
    const unsigned uF = smem_u32(&sF[warp][0][0]);

    for (int t = 0; t < ITERS; ++t) {
        const int i = blockIdx.x * (8 * ITERS) + t * 8 + warp;

        float dcx = 0.0f, dcy = 0.0f, dcz = 0.0f;
        float d1r[2][4][4];   // layer-1 D: [mt][nt][4] (relu'd in place later)

        if (i < N) {
        // ---- gather: one 256-bit load per record ----
        const int nb = dense_l[i * 32 + lane];
        float4 ci, ni, cj, nj;
        ldg256(&g_pt[i],  ci, ni);
        ldg256(&g_pt[nb], cj, nj);

        dcx = cj.x - ci.x; dcy = cj.y - ci.y; dcz = cj.z - ci.z;
        const float invsd = 1.0f / ci.w;
        const float dx = dcx * invsd, dy = dcy * invsd, dz = dcz * invsd;
        const float wo = old_w[i * 32 + lane];
        const float f4 = fabsf(dx*ni.x + dy*ni.y + dz*ni.z);
        const float f5 = fabsf(dx*nj.x + dy*nj.y + dz*nj.z);
        const float f6 = fabsf(ni.x*nj.x + ni.y*nj.y + ni.z*nj.z);
        float f[8];
        f[0] = dx; f[1] = dy; f[2] = dz; f[3] = wo;
        f[4] = f4; f[5] = f5; f[6] = f6; f[7] = 0.0f;

        // ---- stage features to sF: hi + lo residue, 2 STS.128 ----
        {
            uint4 vh, vl;
            unsigned ph; float r0, r1;
            ph = pack2(f[0], f[1]); vh.x = ph; unpack2(ph, r0, r1);
            vl.x = pack2(f[0]-r0, f[1]-r1);
            ph = pack2(f[2], f[3]); vh.y = ph; unpack2(ph, r0, r1);
            vl.y = pack2(f[2]-r0, f[3]-r1);
            ph = pack2(f[4], f[5]); vh.z = ph; unpack2(ph, r0, r1);
            vl.z = pack2(f[4]-r0, f[5]-r1);
            ph = pack2(f[6], f[7]); vh.w = ph; unpack2(ph, r0, r1);
            vl.w = pack2(f[6]-r0, f[7]-r1);
            *(uint4*)&sF[warp][lane][0] = vh;
            *(uint4*)&sF[warp][lane][4] = vl;
        }
        __syncwarp();

        // ---- layer-1 A frags: 2x ldmatrix.x4 (hi, lo); rows = lane ----
        unsigned Ah[4], Al[4];
        {
            const unsigned ah_addr = uF + lane * (FPAD * 4);
            ldsm4(Ah[0], Ah[1], Ah[2], Ah[3], ah_addr);
            ldsm4(Al[0], Al[1], Al[2], Al[3], ah_addr + 16);
        }

        // ---- layer 1 on tensor pipe: D = F@W1 + b1 (3-pass compensation) ----
#pragma unroll
        for (int nt = 0; nt < 4; ++nt) {
            const float2 bv = *(const float2*)&sB1v[nt*8 + 2*lp];
#pragma unroll
            for (int mt = 0; mt < 2; ++mt) {
                d1r[mt][nt][0] = bv.x; d1r[mt][nt][1] = bv.y;
                d1r[mt][nt][2] = bv.x; d1r[mt][nt][3] = bv.y;
            }
        }
#pragma unroll
        for (int nt = 0; nt < 4; ++nt) {
            const unsigned bh = sW1h[nt][lane];
            const unsigned bl = sW1l[nt][lane];
#pragma unroll
            for (int mt = 0; mt < 2; ++mt) {
                mma8h(d1r[mt][nt], Ah[2*mt], Ah[2*mt+1], bh);
                mma8h(d1r[mt][nt], Ah[2*mt], Ah[2*mt+1], bl);
                mma8h(d1r[mt][nt], Al[2*mt], Al[2*mt+1], bh);
            }
        }
        // relu in place
#pragma unroll
        for (int mt = 0; mt < 2; ++mt)
#pragma unroll
            for (int nt = 0; nt < 4; ++nt)
#pragma unroll
                for (int k = 0; k < 4; ++k)
                    d1r[mt][nt][k] = fmaxf(d1r[mt][nt][k], 0.0f);

        // ---- segmax: local max over 4 rows, butterfly over lq lanes ----
        {
            float gmx[8];
#pragma unroll
            for (int nt = 0; nt < 4; ++nt) {
                gmx[2*nt+0] = fmaxf(fmaxf(d1r[0][nt][0], d1r[0][nt][2]),
                                    fmaxf(d1r[1][nt][0], d1r[1][nt][2]));
                gmx[2*nt+1] = fmaxf(fmaxf(d1r[0][nt][1], d1r[0][nt][3]),
                                    fmaxf(d1r[1][nt][1], d1r[1][nt][3]));
            }
#pragma unroll
            for (int s = 4; s < 32; s <<= 1)
#pragma unroll
                for (int k = 0; k < 8; ++k)
                    gmx[k] = fmaxf(gmx[k], __shfl_xor_sync(FULLMASK, gmx[k], s));
            if (lane < 4) {
#pragma unroll
                for (int nt = 0; nt < 4; ++nt)
                    sGh[warp][nt*4 + lp] = pack2(gmx[2*nt+0], gmx[2*nt+1]);
            }
        }
        } // part A (i < N)

        __syncthreads();   // all sGh published

        // ---- batched gd: warp 0 computes gd+b2 for all 8 points ----
        if (warp == 0) {
            unsigned a0k0 = sGh[lq][lp],     a2k0 = sGh[lq][lp + 4];
            unsigned a0k1 = sGh[lq][lp + 8], a2k1 = sGh[lq][lp + 12];
#pragma unroll
            for (int nt = 0; nt < 4; ++nt) {
                float d0 = 0.0f, d1 = 0.0f, dd2 = 0.0f, dd3 = 0.0f;
                {
                    const uint2 bh = *(const uint2*)&sBh[2*4+nt][2*lane];
                    const uint2 bl = *(const uint2*)&sBl[0*4+nt][2*lane];
                    mma16(d0, d1, dd2, dd3, a0k0, a0k0, a2k0, a2k0, bh.x, bh.y);
                    mma16(d0, d1, dd2, dd3, a0k0, a0k0, a2k0, a2k0, bl.x, bl.y);
                }
                {
                    const uint2 bh = *(const uint2*)&sBh[3*4+nt][2*lane];
                    const uint2 bl = *(const uint2*)&sBl[1*4+nt][2*lane];
                    mma16(d0, d1, dd2, dd3, a0k1, a0k1, a2k1, a2k1, bh.x, bh.y);
                    mma16(d0, d1, dd2, dd3, a0k1, a0k1, a2k1, a2k1, bl.x, bl.y);
                }
                const int c0 = nt*8 + 2*lp;
                const float4 ep = *(const float4*)&sEp[2*c0];
                *(float2*)&sGd[lq][c0] = make_float2(d0 + ep.x, d1 + ep.z);
            }
        }

        __syncthreads();   // sGd ready

        if (i < N) {
        // ---- layer-2 A frags packed straight from layer-1 D registers ----
        unsigned ah[16];
#pragma unroll
        for (int mt = 0; mt < 2; ++mt)
#pragma unroll
            for (int kt = 0; kt < 2; ++kt) {
                unsigned* a = &ah[(mt*2+kt)*4];
                a[0] = pack2(d1r[mt][2*kt  ][0], d1r[mt][2*kt  ][1]);
                a[1] = pack2(d1r[mt][2*kt  ][2], d1r[mt][2*kt  ][3]);
                a[2] = pack2(d1r[mt][2*kt+1][0], d1r[mt][2*kt+1][1]);
                a[3] = pack2(d1r[mt][2*kt+1][2], d1r[mt][2*kt+1][3]);
            }

        // ---- layer 2: h @ W2a (g-part from sGd) ----
        float s3p[4] = {0.0f, 0.0f, 0.0f, 0.0f};
#pragma unroll
        for (int nt = 0; nt < 4; ++nt) {
            float d[8] = {0,0,0,0,0,0,0,0};
#pragma unroll
            for (int kt = 0; kt < 2; ++kt) {
                const uint2 b = *(const uint2*)&sBh[kt*4+nt][2*lane];
                const unsigned* a0 = &ah[(0*2+kt)*4];
                const unsigned* a1 = &ah[(1*2+kt)*4];
                mma16(d[0], d[1], d[2], d[3], a0[0], a0[1], a0[2], a0[3], b.x, b.y);
                mma16(d[4], d[5], d[6], d[7], a1[0], a1[1], a1[2], a1[3], b.x, b.y);
            }
            const int c0 = nt*8 + 2*lp;
            const float4 ep = *(const float4*)&sEp[2*c0];     // .y/.w = W3
            const float2 gv = *(const float2*)&sGd[warp][c0]; // gd + b2
            s3p[0] = fmaf(fmaxf(d[0] + gv.x, 0.0f), ep.y, s3p[0]);
            s3p[0] = fmaf(fmaxf(d[1] + gv.y, 0.0f), ep.w, s3p[0]);
            s3p[1] = fmaf(fmaxf(d[2] + gv.x, 0.0f), ep.y, s3p[1]);
            s3p[1] = fmaf(fmaxf(d[3] + gv.y, 0.0f), ep.w, s3p[1]);
            s3p[2] = fmaf(fmaxf(d[4] + gv.x, 0.0f), ep.y, s3p[2]);
            s3p[2] = fmaf(fmaxf(d[5] + gv.y, 0.0f), ep.w, s3p[2]);
            s3p[3] = fmaf(fmaxf(d[6] + gv.x, 0.0f), ep.y, s3p[3]);
            s3p[3] = fmaf(fmaxf(d[7] + gv.y, 0.0f), ep.w, s3p[3]);
        }
#pragma unroll
        for (int k = 0; k < 4; ++k) {
            s3p[k] += __shfl_xor_sync(FULLMASK, s3p[k], 1);
            s3p[k] += __shfl_xor_sync(FULLMASK, s3p[k], 2);
        }
        float wr[4];
#pragma unroll
        for (int k = 0; k < 4; ++k)
            wr[k] = 1.0f / (1.0f + __expf(-(s3p[k] + b3v)));
        if (lp == 0) {
            sG[warp][lq     ] = wr[0];
            sG[warp][lq +  8] = wr[1];
            sG[warp][lq + 16] = wr[2];
            sG[warp][lq + 24] = wr[3];
        }
        __syncwarp();
        const float wgt = sG[warp][lane];

        out_weights[i * 32 + lane] = wgt;

        // ---- weighted covariance butterfly; lane 0 stashes sums ----
        float cxx = wgt*dcx*dcx, cxy = wgt*dcx*dcy, cxz = wgt*dcx*dcz;
        float cyy = wgt*dcy*dcy, cyz = wgt*dcy*dcz, czz = wgt*dcz*dcz;
#pragma unroll
        for (int s = 16; s > 0; s >>= 1) {
            cxx += __shfl_xor_sync(FULLMASK, cxx, s);
            cxy += __shfl_xor_sync(FULLMASK, cxy, s);
            cxz += __shfl_xor_sync(FULLMASK, cxz, s);
            cyy += __shfl_xor_sync(FULLMASK, cyy, s);
            cyz += __shfl_xor_sync(FULLMASK, cyz, s);
            czz += __shfl_xor_sync(FULLMASK, czz, s);
        }
        if (lane == 0) {
            const int slot = t * 8 + warp;
            sCov[slot][0] = cxx; sCov[slot][1] = cxy; sCov[slot][2] = cxz;
            sCov[slot][3] = cyy; sCov[slot][4] = cyz; sCov[slot][5] = czz;
        }
        } // part B (i < N)
    }

    // ---- batched eigensolve: 32 points, lane-parallel on warp 0 ----
    __syncthreads();
    if (warp == 0) {
        const int p = blockIdx.x * 32 + lane;
        if (p < N) {
            const float a00 = sCov[lane][0] + 1e-8f;
            const float a01 = sCov[lane][1];
            const float a02 = sCov[lane][2];
            const float a11 = sCov[lane][3] + 1e-8f;
            const float a12 = sCov[lane][4];
            const float a22 = sCov[lane][5] + 1e-8f;

            const float q = (a00 + a11 + a22) / 3.0f;
            const float b00 = a00 - q, b11 = a11 - q, b22 = a22 - q;
            const float ss = b00*b00 + b11*b11 + b22*b22
                           + 2.0f*(a01*a01 + a02*a02 + a12*a12);
            const float pp = sqrtf(ss / 6.0f) + 1e-20f;

            const float B00 = b00/pp, B11 = b11/pp, B22 = b22/pp;
            const float B01 = a01/pp, B02 = a02/pp, B12 = a12/pp;
            const float det = B00*(B11*B22 - B12*B12)
                            - B01*(B01*B22 - B12*B02)
                            + B02*(B01*B12 - B11*B02);
            float r = det / 2.0f;
            r = fminf(fmaxf(r, -1.0f + 1e-7f), 1.0f - 1e-7f);
            const float phi = acosf(r) / 3.0f;
            const float e1 = q + 2.0f*pp*cosf(phi);
            const float e3 = q + 2.0f*pp*cosf(phi + 2.0943951023931953f);
            const float e2 = 3.0f*q - e1 - e3;

            float lam = e1, ab = fabsf(e1);
            if (fabsf(e2) < ab) { lam = e2; ab = fabsf(e2); }
            if (fabsf(e3) < ab) { lam = e3; }

            const float m00 = a00 - lam, m11 = a11 - lam, m22 = a22 - lam;
            const float c0x = a01*a12 - a02*m11;
            const float c0y = a02*a01 - m00*a12;
            const float c0z = m00*m11 - a01*a01;
            const float c1x = m11*m22 - a12*a12;
            const float c1y = a12*a02 - a01*m22;
            const float c1z = a01*a12 - m11*a02;
            const float c2x = a12*a02 - m22*a01;
            const float c2y = m22*m00 - a02*a02;
            const float c2z = a02*a01 - a12*m00;

            const float n0 = sqrtf(c0x*c0x + c0y*c0y + c0z*c0z);
            const float n1 = sqrtf(c1x*c1x + c1y*c1y + c1z*c1z);
            const float n2 = sqrtf(c2x*c2x + c2y*c2y + c2z*c2z);

            float vx = c0x, vy = c0y, vz = c0z, bn = n0;
            if (n1 > bn) { vx = c1x; vy = c1y; vz = c1z; bn = n1; }
            if (n2 > bn) { vx = c2x; vy = c2y; vz = c2z; }

            const float nv = sqrtf(vx*vx + vy*vy + vz*vz) + 1e-12f;
            out_normals[3*p+0] = vx / nv;
            out_normals[3*p+1] = vy / nv;
            out_normals[3*p+2] = vz / nv;
        }
    }
}

extern "C" void kernel_launch(void* const* d_in, const int* in_sizes, int n_in,
                              void* d_out, int out_size)
{
    const float* old_w   = (const float*)d_in[0];
    const float* pos     = (const float*)d_in[1];
    const float* normals = (const float*)d_in[3];
    const int*   dense_l = (const int*)d_in[5];
    const float* stddev  = (const float*)d_in[6];
    const float* W1      = (const float*)d_in[7];
    const float* b1      = (const float*)d_in[8];
    const float* W2      = (const float*)d_in[9];
    const float* b2      = (const float*)d_in[10];
    const float* W3      = (const float*)d_in[11];
    const float* b3      = (const float*)d_in[12];

    const int N = in_sizes[1] / 3;

    float* out         = (float*)d_out;
    float* out_normals = out;
    float* out_weights = out + (size_t)N * 3;

    pack_kernel<<<(N + 255) / 256, 256>>>(pos, normals, stddev, N);

    const int pts_per_cta = 8 * ITERS;
    dim3 block(256);
    dim3 grid((N + pts_per_cta - 1) / pts_per_cta);
    normal_est_kernel<<<grid, block>>>(old_w, dense_l, W1, b1, W2, b2, W3, b3,
                                       out_normals, out_weights, N);
}

// round 17
// speedup vs baseline: 1.0719x; 1.0719x over previous
#include <cuda_runtime.h>

#define FULLMASK 0xffffffffu
#define ITERS 4   // points per warp; CTA covers 32 points
#define HPAD 20   // half2-words per sHu row (80B, conflict-free)

// ---- layer-1 weights in constant memory (uniform LDC path) ----
__constant__ float cW1[7 * 32];
__constant__ float cB1[32];

// ---- packed per-point data: one 32B-aligned record ----
struct __align__(32) PtData { float4 c; float4 n; };
__device__ PtData g_pt[50048];

__global__ __launch_bounds__(256) void pack_kernel(
    const float* __restrict__ pos,
    const float* __restrict__ normals,
    const float* __restrict__ stddev,
    int N)
{
    int i = blockIdx.x * 256 + threadIdx.x;
    if (i >= N) return;
    float4 a, b;
    a.x = pos[3*i+0]; a.y = pos[3*i+1]; a.z = pos[3*i+2]; a.w = stddev[i];
    b.x = normals[3*i+0]; b.y = normals[3*i+1]; b.z = normals[3*i+2]; b.w = 0.0f;
    g_pt[i].c = a;
    g_pt[i].n = b;
}

__device__ __forceinline__ void ldg256(const PtData* p, float4& a, float4& b) {
    asm("ld.global.nc.v8.f32 {%0,%1,%2,%3,%4,%5,%6,%7}, [%8];"
        : "=f"(a.x), "=f"(a.y), "=f"(a.z), "=f"(a.w),
          "=f"(b.x), "=f"(b.y), "=f"(b.z), "=f"(b.w)
        : "l"(p));
}
__device__ __forceinline__ unsigned pack2(float lo, float hi) {
    unsigned r;
    asm("cvt.rn.f16x2.f32 %0, %1, %2;" : "=r"(r) : "f"(hi), "f"(lo));
    return r;
}
__device__ __forceinline__ void unpack2(unsigned v, float& lo, float& hi) {
    asm("{ .reg .f16 l, h; mov.b32 {l, h}, %2; cvt.f32.f16 %0, l; cvt.f32.f16 %1, h; }"
        : "=f"(lo), "=f"(hi) : "r"(v));
}
__device__ __forceinline__ unsigned hmax2(unsigned a, unsigned b) {
    unsigned r; asm("max.f16x2 %0, %1, %2;" : "=r"(r) : "r"(a), "r"(b)); return r;
}
__device__ __forceinline__ unsigned smem_u32(const void* p) {
    unsigned a;
    asm("{ .reg .u64 t; cvta.to.shared.u64 t, %1; cvt.u32.u64 %0, t; }" : "=r"(a) : "l"(p));
    return a;
}
__device__ __forceinline__ void ldsm4(unsigned& r0, unsigned& r1,
                                      unsigned& r2, unsigned& r3, unsigned addr) {
    asm volatile("ldmatrix.sync.aligned.m8n8.x4.shared.b16 {%0,%1,%2,%3}, [%4];"
        : "=r"(r0), "=r"(r1), "=r"(r2), "=r"(r3) : "r"(addr));
}
__device__ __forceinline__ void mma16(float& d0, float& d1, float& d2, float& d3,
                                      unsigned a0, unsigned a1, unsigned a2, unsigned a3,
                                      unsigned b0, unsigned b1) {
    asm volatile(
        "mma.sync.aligned.m16n8k16.row.col.f32.f16.f16.f32 "
        "{%0,%1,%2,%3}, {%4,%5,%6,%7}, {%8,%9}, {%0,%1,%2,%3};"
        : "+f"(d0), "+f"(d1), "+f"(d2), "+f"(d3)
        : "r"(a0), "r"(a1), "r"(a2), "r"(a3), "r"(b0), "r"(b1));
}

__global__ __launch_bounds__(256, 4) void normal_est_kernel(
    const float* __restrict__ old_w,    // N*32
    const int*   __restrict__ dense_l,  // N*32
    const float* __restrict__ W2g,      // (64,32)
    const float* __restrict__ b2g,      // (32,)
    const float* __restrict__ W3g,      // (32,)
    const float* __restrict__ b3g,      // (1,)
    float* __restrict__ out_normals,
    float* __restrict__ out_weights,
    int N)
{
    __shared__ __align__(16) unsigned sHu[8][32][HPAD]; // per-warp h rows, f16x2
    __shared__ unsigned sBh[16][64];    // B frags interleaved [frag][2*lane..], f16 hi
    __shared__ unsigned sBl[8][64];     // W2b low-residue frags (kt 2..3)
    __shared__ unsigned sGh[8][16];     // per-warp g as f16x2 pairs
    __shared__ __align__(16) float sGd[8][68];  // fused {gd+b2, W3} quads per point
    __shared__ __align__(16) float sG[8][32];   // wgt redistribution
    __shared__ __align__(16) float sEp[64];     // interleaved [b2[j], W3[j]] (warp0 use)
    __shared__            float    sB3;
    __shared__            float    sCov[32][8];

    const int tid  = threadIdx.x;
    const int lane = tid & 31;
    const int warp = tid >> 5;
    const int lp   = lane & 3;      // quad-lane
    const int lq   = lane >> 2;     // quad-row

    // B fragments (m16n8k16 row.col), full K=64 of W2; hi = f16, lo residue for kt>=2
    for (int it = tid; it < 512; it += 256) {
        const int frag = it >> 5, l2 = it & 31;
        const int lp2 = l2 & 3, lq2 = l2 >> 2;
        const int kt = frag >> 2, nt = frag & 3;
        const int n  = nt * 8 + lq2;
        const int k0 = kt * 16 + 2 * lp2;
        const float w00 = W2g[(k0    ) * 32 + n], w01 = W2g[(k0 + 1) * 32 + n];
        const float w10 = W2g[(k0 + 8) * 32 + n], w11 = W2g[(k0 + 9) * 32 + n];
        const unsigned p0 = pack2(w00, w01), p1 = pack2(w10, w11);
        sBh[frag][2*l2  ] = p0;
        sBh[frag][2*l2+1] = p1;
        if (kt >= 2) {
            float r00, r01, r10, r11;
            unpack2(p0, r00, r01); unpack2(p1, r10, r11);
            sBl[frag-8][2*l2  ] = pack2(w00 - r00, w01 - r01);
            sBl[frag-8][2*l2+1] = pack2(w10 - r10, w11 - r11);
        }
    }
    if (tid < 32) { sEp[2*tid] = b2g[tid]; sEp[2*tid+1] = W3g[tid]; }
    if (tid == 0) sB3 = b3g[0];
    __syncthreads();

    const float b3v = sB3;

    // ldmatrix lane address components (fixed per thread)
    const unsigned uH   = smem_u32(&sHu[warp][0][0]);
    const unsigned rb   = lane & 15;            // row within 16-row block
    const unsigned woff = (lane >> 4) * 4;      // +4 words for k8..15 matrices

    for (int t = 0; t < ITERS; ++t) {
        const int i = blockIdx.x * (8 * ITERS) + t * 8 + warp;

        // saved across part A -> part B
        float dcx = 0.0f, dcy = 0.0f, dcz = 0.0f;

        if (i < N) {
        // ---- gather: one 256-bit load per record ----
        const int nb = dense_l[i * 32 + lane];
        const float wo = old_w[i * 32 + lane];
        float4 ci, ni, cj, nj;
        ldg256(&g_pt[i],  ci, ni);
        ldg256(&g_pt[nb], cj, nj);

        dcx = cj.x - ci.x; dcy = cj.y - ci.y; dcz = cj.z - ci.z;
        const float invsd = 1.0f / ci.w;
        const float dx = dcx * invsd, dy = dcy * invsd, dz = dcz * invsd;
        const float f4 = fabsf(dx*ni.x + dy*ni.y + dz*ni.z);
        const float f5 = fabsf(dx*nj.x + dy*nj.y + dz*nj.z);
        const float f6 = fabsf(ni.x*nj.x + ni.y*nj.y + ni.z*nj.z);
        float f[7];
        f[0] = dx; f[1] = dy; f[2] = dz; f[3] = wo; f[4] = f4; f[5] = f5; f[6] = f6;

        // ---- layer 1 (constant port); store f16x2 rows via STS.128 ----
#pragma unroll
        for (int jh = 0; jh < 2; ++jh) {
            float h[16];
#pragma unroll
            for (int k = 0; k < 16; k += 4) {
                const float4 bv = *(const float4*)&cB1[jh*16 + k];
                h[k+0] = bv.x; h[k+1] = bv.y; h[k+2] = bv.z; h[k+3] = bv.w;
            }
#pragma unroll
            for (int in = 0; in < 7; ++in) {
                const float fv = f[in];
#pragma unroll
                for (int k = 0; k < 16; k += 4) {
                    const float4 wv = *(const float4*)&cW1[in*32 + jh*16 + k];
                    h[k+0] = fmaf(fv, wv.x, h[k+0]);
                    h[k+1] = fmaf(fv, wv.y, h[k+1]);
                    h[k+2] = fmaf(fv, wv.z, h[k+2]);
                    h[k+3] = fmaf(fv, wv.w, h[k+3]);
                }
            }
#pragma unroll
            for (int q = 0; q < 2; ++q) {
                uint4 v;
                v.x = pack2(fmaxf(h[8*q+0], 0.0f), fmaxf(h[8*q+1], 0.0f));
                v.y = pack2(fmaxf(h[8*q+2], 0.0f), fmaxf(h[8*q+3], 0.0f));
                v.z = pack2(fmaxf(h[8*q+4], 0.0f), fmaxf(h[8*q+5], 0.0f));
                v.w = pack2(fmaxf(h[8*q+6], 0.0f), fmaxf(h[8*q+7], 0.0f));
                *(uint4*)&sHu[warp][lane][jh*8 + 4*q] = v;
            }
        }
        __syncwarp();

        // ---- segment max over 32 rows (f16x2); publish g pairs to sGh ----
        {
            const int pr = lane & 15;
            const int ro = lane >> 4;
            unsigned m2 = sHu[warp][ro][pr];
#pragma unroll
            for (int k = 1; k < 16; ++k)
                m2 = hmax2(m2, sHu[warp][2*k + ro][pr]);
            const unsigned other =
                __shfl_sync(FULLMASK, m2, pr + ((lane < 16) ? 16 : 0));
            m2 = hmax2(m2, other);
            if (lane < 16) sGh[warp][pr] = m2;
        }
        } // part A (i < N)

        __syncthreads();   // all sGh published

        // ---- batched gd: warp 0 computes {gd+b2, W3} for all 8 points ----
        if (warp == 0) {
            unsigned a0k0 = sGh[lq][lp],     a2k0 = sGh[lq][lp + 4];
            unsigned a0k1 = sGh[lq][lp + 8], a2k1 = sGh[lq][lp + 12];
#pragma unroll
            for (int nt = 0; nt < 4; ++nt) {
                float d0 = 0.0f, d1 = 0.0f, dd2 = 0.0f, dd3 = 0.0f;
                {
                    const uint2 bh = *(const uint2*)&sBh[2*4+nt][2*lane];
                    const uint2 bl = *(const uint2*)&sBl[0*4+nt][2*lane];
                    mma16(d0, d1, dd2, dd3, a0k0, a0k0, a2k0, a2k0, bh.x, bh.y);
                    mma16(d0, d1, dd2, dd3, a0k0, a0k0, a2k0, a2k0, bl.x, bl.y);
                }
                {
                    const uint2 bh = *(const uint2*)&sBh[3*4+nt][2*lane];
                    const uint2 bl = *(const uint2*)&sBl[1*4+nt][2*lane];
                    mma16(d0, d1, dd2, dd3, a0k1, a0k1, a2k1, a2k1, bh.x, bh.y);
                    mma16(d0, d1, dd2, dd3, a0k1, a0k1, a2k1, a2k1, bl.x, bl.y);
                }
                const int c0 = nt*8 + 2*lp;
                const float4 ep = *(const float4*)&sEp[2*c0];
                // fused quad: {gd0+b2, W3, gd1+b2', W3'}
                *(float4*)&sGd[lq][2*c0] =
                    make_float4(d0 + ep.x, ep.y, d1 + ep.z, ep.w);
            }
        }

        __syncthreads();   // sGd ready

        if (i < N) {
        // ---- A fragments via ldmatrix.x4 ----
        unsigned ah[16];
#pragma unroll
        for (int mt = 0; mt < 2; ++mt)
#pragma unroll
            for (int kt = 0; kt < 2; ++kt) {
                const unsigned addr =
                    uH + (((mt*16 + rb) * HPAD + kt*8 + woff) << 2);
                unsigned* a = &ah[(mt*2+kt)*4];
                ldsm4(a[0], a[1], a[2], a[3], addr);
            }

        // ---- layer 2: h @ W2a only (g-part + W3 come fused from sGd) ----
        float s3p[4] = {0.0f, 0.0f, 0.0f, 0.0f};
#pragma unroll
        for (int nt = 0; nt < 4; ++nt) {
            float d[8] = {0,0,0,0,0,0,0,0};
#pragma unroll
            for (int kt = 0; kt < 2; ++kt) {
                const uint2 b = *(const uint2*)&sBh[kt*4+nt][2*lane];
                const unsigned* a0 = &ah[(0*2+kt)*4];
                const unsigned* a1 = &ah[(1*2+kt)*4];
                mma16(d[0], d[1], d[2], d[3], a0[0], a0[1], a0[2], a0[3], b.x, b.y);
                mma16(d[4], d[5], d[6], d[7], a1[0], a1[1], a1[2], a1[3], b.x, b.y);
            }
            const int c0 = nt*8 + 2*lp;
            const float4 gw4 = *(const float4*)&sGd[warp][2*c0]; // {gd,W3,gd',W3'}
            s3p[0] = fmaf(fmaxf(d[0] + gw4.x, 0.0f), gw4.y, s3p[0]);
            s3p[0] = fmaf(fmaxf(d[1] + gw4.z, 0.0f), gw4.w, s3p[0]);
            s3p[1] = fmaf(fmaxf(d[2] + gw4.x, 0.0f), gw4.y, s3p[1]);
            s3p[1] = fmaf(fmaxf(d[3] + gw4.z, 0.0f), gw4.w, s3p[1]);
            s3p[2] = fmaf(fmaxf(d[4] + gw4.x, 0.0f), gw4.y, s3p[2]);
            s3p[2] = fmaf(fmaxf(d[5] + gw4.z, 0.0f), gw4.w, s3p[2]);
            s3p[3] = fmaf(fmaxf(d[6] + gw4.x, 0.0f), gw4.y, s3p[3]);
            s3p[3] = fmaf(fmaxf(d[7] + gw4.z, 0.0f), gw4.w, s3p[3]);
        }
#pragma unroll
        for (int k = 0; k < 4; ++k) {
            s3p[k] += __shfl_xor_sync(FULLMASK, s3p[k], 1);
            s3p[k] += __shfl_xor_sync(FULLMASK, s3p[k], 2);
        }
        float wr[4];
#pragma unroll
        for (int k = 0; k < 4; ++k)
            wr[k] = 1.0f / (1.0f + __expf(-(s3p[k] + b3v)));
        if (lp == 0) {
            sG[warp][lq     ] = wr[0];
            sG[warp][lq +  8] = wr[1];
            sG[warp][lq + 16] = wr[2];
            sG[warp][lq + 24] = wr[3];
        }
        __syncwarp();
        const float wgt = sG[warp][lane];

        out_weights[i * 32 + lane] = wgt;

        // ---- weighted covariance butterfly; lane 0 stashes sums ----
        float cxx = wgt*dcx*dcx, cxy = wgt*dcx*dcy, cxz = wgt*dcx*dcz;
        float cyy = wgt*dcy*dcy, cyz = wgt*dcy*dcz, czz = wgt*dcz*dcz;
#pragma unroll
        for (int s = 16; s > 0; s >>= 1) {
            cxx += __shfl_xor_sync(FULLMASK, cxx, s);
            cxy += __shfl_xor_sync(FULLMASK, cxy, s);
            cxz += __shfl_xor_sync(FULLMASK, cxz, s);
            cyy += __shfl_xor_sync(FULLMASK, cyy, s);
            cyz += __shfl_xor_sync(FULLMASK, cyz, s);
            czz += __shfl_xor_sync(FULLMASK, czz, s);
        }
        if (lane == 0) {
            const int slot = t * 8 + warp;
            sCov[slot][0] = cxx; sCov[slot][1] = cxy; sCov[slot][2] = cxz;
            sCov[slot][3] = cyy; sCov[slot][4] = cyz; sCov[slot][5] = czz;
        }
        } // part B (i < N)
    }

    // ---- batched eigensolve: 32 points, lane-parallel on warp 0 ----
    __syncthreads();
    if (warp == 0) {
        const int p = blockIdx.x * 32 + lane;
        if (p < N) {
            const float a00 = sCov[lane][0] + 1e-8f;
            const float a01 = sCov[lane][1];
            const float a02 = sCov[lane][2];
            const float a11 = sCov[lane][3] + 1e-8f;
            const float a12 = sCov[lane][4];
            const float a22 = sCov[lane][5] + 1e-8f;

            const float q = (a00 + a11 + a22) / 3.0f;
            const float b00 = a00 - q, b11 = a11 - q, b22 = a22 - q;
            const float ss = b00*b00 + b11*b11 + b22*b22
                           + 2.0f*(a01*a01 + a02*a02 + a12*a12);
            const float pp = sqrtf(ss / 6.0f) + 1e-20f;

            const float B00 = b00/pp, B11 = b11/pp, B22 = b22/pp;
            const float B01 = a01/pp, B02 = a02/pp, B12 = a12/pp;
            const float det = B00*(B11*B22 - B12*B12)
                            - B01*(B01*B22 - B12*B02)
                            + B02*(B01*B12 - B11*B02);
            float r = det / 2.0f;
            r = fminf(fmaxf(r, -1.0f + 1e-7f), 1.0f - 1e-7f);
            const float phi = acosf(r) / 3.0f;
            const float e1 = q + 2.0f*pp*cosf(phi);
            const float e3 = q + 2.0f*pp*cosf(phi + 2.0943951023931953f);
            const float e2 = 3.0f*q - e1 - e3;

            float lam = e1, ab = fabsf(e1);
            if (fabsf(e2) < ab) { lam = e2; ab = fabsf(e2); }
            if (fabsf(e3) < ab) { lam = e3; }

            const float m00 = a00 - lam, m11 = a11 - lam, m22 = a22 - lam;
            const float c0x = a01*a12 - a02*m11;
            const float c0y = a02*a01 - m00*a12;
            const float c0z = m00*m11 - a01*a01;
            const float c1x = m11*m22 - a12*a12;
            const float c1y = a12*a02 - a01*m22;
            const float c1z = a01*a12 - m11*a02;
            const float c2x = a12*a02 - m22*a01;
            const float c2y = m22*m00 - a02*a02;
            const float c2z = a02*a01 - a12*m00;

            const float n0 = sqrtf(c0x*c0x + c0y*c0y + c0z*c0z);
            const float n1 = sqrtf(c1x*c1x + c1y*c1y + c1z*c1z);
            const float n2 = sqrtf(c2x*c2x + c2y*c2y + c2z*c2z);

            float vx = c0x, vy = c0y, vz = c0z, bn = n0;
            if (n1 > bn) { vx = c1x; vy = c1y; vz = c1z; bn = n1; }
            if (n2 > bn) { vx = c2x; vy = c2y; vz = c2z; }

            const float nv = sqrtf(vx*vx + vy*vy + vz*vz) + 1e-12f;
            out_normals[3*p+0] = vx / nv;
            out_normals[3*p+1] = vy / nv;
            out_normals[3*p+2] = vz / nv;
        }
    }
}

extern "C" void kernel_launch(void* const* d_in, const int* in_sizes, int n_in,
                              void* d_out, int out_size)
{
    const float* old_w   = (const float*)d_in[0];
    const float* pos     = (const float*)d_in[1];
    const float* normals = (const float*)d_in[3];
    const int*   dense_l = (const int*)d_in[5];
    const float* stddev  = (const float*)d_in[6];
    const float* W1      = (const float*)d_in[7];
    const float* b1      = (const float*)d_in[8];
    const float* W2      = (const float*)d_in[9];
    const float* b2      = (const float*)d_in[10];
    const float* W3      = (const float*)d_in[11];
    const float* b3      = (const float*)d_in[12];

    const int N = in_sizes[1] / 3;

    // only the hot layer-1 weights go to constant memory (2 graph nodes)
    cudaMemcpyToSymbolAsync(cW1, W1, 7 * 32 * sizeof(float), 0, cudaMemcpyDeviceToDevice);
    cudaMemcpyToSymbolAsync(cB1, b1, 32 * sizeof(float),     0, cudaMemcpyDeviceToDevice);

    float* out         = (float*)d_out;
    float* out_normals = out;
    float* out_weights = out + (size_t)N * 3;

    pack_kernel<<<(N + 255) / 256, 256>>>(pos, normals, stddev, N);

    const int pts_per_cta = 8 * ITERS;
    dim3 block(256);
    dim3 grid((N + pts_per_cta - 1) / pts_per_cta);
    normal_est_kernel<<<grid, block>>>(old_w, dense_l, W2, b2, W3, b3,
                                       out_normals, out_weights, N);
}